// round 1
// baseline (speedup 1.0000x reference)
#include <cuda_runtime.h>
#include <math.h>

// Problem constants (fixed shapes from reference setup_inputs)
#define OUT_N  2048
#define IN_K   2048
#define M_ROWS 8192   // B*S = 4*2048
#define RANK   4
#define LUT_L  16

// Scratch (static __device__ globals — no runtime allocation)
__device__ float g_aScaled[OUT_N * RANK];   // |A[o,r]| * g[r] / ||A[:,r]||
__device__ float g_bScaled[RANK * IN_K];    // |B[r,i]| / ||B[r,:]||
__device__ float g_W[(size_t)OUT_N * IN_K]; // effective weight, 16 MB

// ---------------------------------------------------------------------------
// Kernel 1: rank-4 norms + softplus magnitudes, write scaled factor arrays
// ---------------------------------------------------------------------------
__global__ __launch_bounds__(256) void prep_kernel(const float* __restrict__ sA,
                                                   const float* __restrict__ sB,
                                                   const float* __restrict__ mag)
{
    __shared__ float red[256];
    __shared__ float coefA[RANK];
    __shared__ float coefB[RANK];
    const int tid = threadIdx.x;

    for (int r = 0; r < RANK; ++r) {
        // ||A[:,r]||^2
        float s = 0.f;
        for (int o = tid; o < OUT_N; o += 256) {
            float v = sA[o * RANK + r];
            s += v * v;
        }
        red[tid] = s;
        __syncthreads();
        for (int off = 128; off > 0; off >>= 1) {
            if (tid < off) red[tid] += red[tid + off];
            __syncthreads();
        }
        if (tid == 0) {
            float nrm = fmaxf(sqrtf(red[0]), 1e-6f);
            float m = mag[r];
            float g = (m > 20.f ? m : log1pf(expf(m))) + 1e-6f; // softplus + eps
            coefA[r] = g / nrm;
        }
        __syncthreads();

        // ||B[r,:]||^2
        s = 0.f;
        for (int i = tid; i < IN_K; i += 256) {
            float v = sB[r * IN_K + i];
            s += v * v;
        }
        red[tid] = s;
        __syncthreads();
        for (int off = 128; off > 0; off >>= 1) {
            if (tid < off) red[tid] += red[tid + off];
            __syncthreads();
        }
        if (tid == 0) coefB[r] = 1.f / fmaxf(sqrtf(red[0]), 1e-6f);
        __syncthreads();
    }

    // Write scaled factors
    for (int idx = tid; idx < OUT_N * RANK; idx += 256)
        g_aScaled[idx] = fabsf(sA[idx]) * coefA[idx & (RANK - 1)];
    for (int idx = tid; idx < RANK * IN_K; idx += 256)
        g_bScaled[idx] = fabsf(sB[idx]) * coefB[idx >> 11]; // idx / IN_K
}

// ---------------------------------------------------------------------------
// Kernel 2: materialize W[o,i] = lut[indices[o,i]] * dot4(a[o,:], b[:,i])
// One block per output row; 512 threads x 4 elements.
// ---------------------------------------------------------------------------
__global__ __launch_bounds__(512) void build_w_kernel(const int* __restrict__ indices,
                                                      const float* __restrict__ lut)
{
    __shared__ float lsh[LUT_L];
    __shared__ float ash[RANK];
    const int o = blockIdx.x;
    const int tid = threadIdx.x;
    if (tid < LUT_L) lsh[tid] = lut[tid];
    if (tid < RANK)  ash[tid] = g_aScaled[o * RANK + tid];
    __syncthreads();

    const float a0 = ash[0], a1 = ash[1], a2 = ash[2], a3 = ash[3];
    const int i0 = tid * 4;
    const int4 idx = *(const int4*)&indices[(size_t)o * IN_K + i0];
    const float4 b0 = *(const float4*)&g_bScaled[0 * IN_K + i0];
    const float4 b1 = *(const float4*)&g_bScaled[1 * IN_K + i0];
    const float4 b2 = *(const float4*)&g_bScaled[2 * IN_K + i0];
    const float4 b3 = *(const float4*)&g_bScaled[3 * IN_K + i0];

    float4 w;
    w.x = lsh[idx.x] * (a0 * b0.x + a1 * b1.x + a2 * b2.x + a3 * b3.x);
    w.y = lsh[idx.y] * (a0 * b0.y + a1 * b1.y + a2 * b2.y + a3 * b3.y);
    w.z = lsh[idx.z] * (a0 * b0.z + a1 * b1.z + a2 * b2.z + a3 * b3.z);
    w.w = lsh[idx.w] * (a0 * b0.w + a1 * b1.w + a2 * b2.w + a3 * b3.w);
    *(float4*)&g_W[(size_t)o * IN_K + i0] = w;
}

// ---------------------------------------------------------------------------
// Kernel 3: SGEMM  Y[M, N] = X[M, K] * W[N, K]^T + bias[N]
// 128x128 block tile, BK=16, 8x8 per-thread micro-tile (split 4+4), 256 thr.
// ---------------------------------------------------------------------------
#define BM 128
#define BN 128
#define BK 16

__global__ __launch_bounds__(256, 2) void sgemm_nt_kernel(const float* __restrict__ X,
                                                          const float* __restrict__ bias,
                                                          float* __restrict__ Y)
{
    __shared__ float As[BK][BM];
    __shared__ float Bs[BK][BN];

    const int tid = threadIdx.x;
    const int bm = blockIdx.y * BM;
    const int bn = blockIdx.x * BN;

    // global->shared load mapping: 256 threads, each loads 2 float4 per tile
    const int lr = tid >> 2;            // 0..63
    const int lc = (tid & 3) << 2;      // 0,4,8,12

    // compute mapping: 16x16 thread grid, 4+4 split rows/cols
    const int tr = ((tid >> 4) & 15) << 2;  // 0..60
    const int tc = (tid & 15) << 2;         // 0..60

    const float* Xp = X + (size_t)bm * IN_K;
    const float* Wp = g_W + (size_t)bn * IN_K;

    float acc[8][8];
#pragma unroll
    for (int i = 0; i < 8; ++i)
#pragma unroll
        for (int j = 0; j < 8; ++j) acc[i][j] = 0.f;

    for (int kt = 0; kt < IN_K; kt += BK) {
        const float4 xa = *(const float4*)&Xp[(size_t)lr * IN_K + kt + lc];
        const float4 xb = *(const float4*)&Xp[(size_t)(lr + 64) * IN_K + kt + lc];
        const float4 wa = *(const float4*)&Wp[(size_t)lr * IN_K + kt + lc];
        const float4 wb = *(const float4*)&Wp[(size_t)(lr + 64) * IN_K + kt + lc];

        As[lc + 0][lr] = xa.x; As[lc + 1][lr] = xa.y;
        As[lc + 2][lr] = xa.z; As[lc + 3][lr] = xa.w;
        As[lc + 0][lr + 64] = xb.x; As[lc + 1][lr + 64] = xb.y;
        As[lc + 2][lr + 64] = xb.z; As[lc + 3][lr + 64] = xb.w;

        Bs[lc + 0][lr] = wa.x; Bs[lc + 1][lr] = wa.y;
        Bs[lc + 2][lr] = wa.z; Bs[lc + 3][lr] = wa.w;
        Bs[lc + 0][lr + 64] = wb.x; Bs[lc + 1][lr + 64] = wb.y;
        Bs[lc + 2][lr + 64] = wb.z; Bs[lc + 3][lr + 64] = wb.w;

        __syncthreads();

#pragma unroll
        for (int k = 0; k < BK; ++k) {
            const float4 a0 = *(const float4*)&As[k][tr];
            const float4 a1 = *(const float4*)&As[k][tr + 64];
            const float4 b0 = *(const float4*)&Bs[k][tc];
            const float4 b1 = *(const float4*)&Bs[k][tc + 64];
            const float am[8] = {a0.x, a0.y, a0.z, a0.w, a1.x, a1.y, a1.z, a1.w};
            const float bv[8] = {b0.x, b0.y, b0.z, b0.w, b1.x, b1.y, b1.z, b1.w};
#pragma unroll
            for (int i = 0; i < 8; ++i)
#pragma unroll
                for (int j = 0; j < 8; ++j)
                    acc[i][j] = fmaf(am[i], bv[j], acc[i][j]);
        }
        __syncthreads();
    }

    // epilogue: add bias, store float4s
#pragma unroll
    for (int ih = 0; ih < 2; ++ih) {
#pragma unroll
        for (int i = 0; i < 4; ++i) {
            const int row = bm + tr + ih * 64 + i;
#pragma unroll
            for (int jh = 0; jh < 2; ++jh) {
                const int col = bn + tc + jh * 64;
                float4 r;
                r.x = acc[ih * 4 + i][jh * 4 + 0] + bias[col + 0];
                r.y = acc[ih * 4 + i][jh * 4 + 1] + bias[col + 1];
                r.z = acc[ih * 4 + i][jh * 4 + 2] + bias[col + 2];
                r.w = acc[ih * 4 + i][jh * 4 + 3] + bias[col + 3];
                *(float4*)&Y[(size_t)row * OUT_N + col] = r;
            }
        }
    }
}

// ---------------------------------------------------------------------------
// Launch
// ---------------------------------------------------------------------------
extern "C" void kernel_launch(void* const* d_in, const int* in_sizes, int n_in,
                              void* d_out, int out_size)
{
    const float* x       = (const float*)d_in[0];  // [4, 2048, 2048]
    const int*   indices = (const int*)  d_in[1];  // [2048, 2048]
    const float* lut     = (const float*)d_in[2];  // [16]
    const float* sA      = (const float*)d_in[3];  // [2048, 4]
    const float* sB      = (const float*)d_in[4];  // [4, 2048]
    const float* mag     = (const float*)d_in[5];  // [4]
    const float* bias    = (const float*)d_in[6];  // [2048]
    float* y = (float*)d_out;                      // [4, 2048, 2048]

    prep_kernel<<<1, 256>>>(sA, sB, mag);
    build_w_kernel<<<OUT_N, 512>>>(indices, lut);

    dim3 grid(OUT_N / BN, M_ROWS / BM);  // (16, 64)
    sgemm_nt_kernel<<<grid, 256>>>(x, bias, y);
}

// round 3
// speedup vs baseline: 2.8722x; 2.8722x over previous
#include <cuda_runtime.h>
#include <math.h>
#include <stdint.h>

#define OUT_N  2048
#define IN_K   2048
#define M_ROWS 8192
#define RANK   4

// ---------------- scratch (static device globals; no runtime alloc) --------
__device__ float g_aScaled[OUT_N * RANK];
__device__ float g_bScaled[RANK * IN_K];
__device__ float g_W[(size_t)OUT_N * IN_K];   // tf32-rounded effective weight
__device__ float g_X[(size_t)M_ROWS * IN_K];  // tf32-rounded activations

__device__ __forceinline__ float tf32r(float x) {
    float y;
    asm("cvt.rna.tf32.f32 %0, %1;" : "=f"(y) : "f"(x));
    return y;
}

// ---------------- Kernel 1: rank norms + softplus (warp per rank) -----------
__global__ __launch_bounds__(256) void prep_kernel(const float* __restrict__ sA,
                                                   const float* __restrict__ sB,
                                                   const float* __restrict__ mag)
{
    __shared__ float cA[RANK], cB[RANK];
    const int tid = threadIdx.x, wid = tid >> 5, lid = tid & 31;
    if (wid < 4) {
        const int r = wid;
        float s = 0.f;
        for (int o = lid; o < OUT_N; o += 32) { float v = sA[o * RANK + r]; s += v * v; }
        for (int off = 16; off; off >>= 1) s += __shfl_xor_sync(0xffffffff, s, off);
        if (lid == 0) {
            float nrm = fmaxf(sqrtf(s), 1e-6f);
            float m = mag[r];
            float g = (m > 20.f ? m : log1pf(expf(m))) + 1e-6f;
            cA[r] = g / nrm;
        }
    } else {
        const int r = wid - 4;
        float s = 0.f;
        for (int i = lid; i < IN_K; i += 32) { float v = sB[r * IN_K + i]; s += v * v; }
        for (int off = 16; off; off >>= 1) s += __shfl_xor_sync(0xffffffff, s, off);
        if (lid == 0) cB[r] = 1.f / fmaxf(sqrtf(s), 1e-6f);
    }
    __syncthreads();
    for (int idx = tid; idx < OUT_N * RANK; idx += 256)
        g_aScaled[idx] = fabsf(sA[idx]) * cA[idx & 3];
    for (int idx = tid; idx < RANK * IN_K; idx += 256)
        g_bScaled[idx] = fabsf(sB[idx]) * cB[idx >> 11];
}

// ---------------- Kernel 2: W = round_tf32(lut[idx] * dot4(a,b)) ------------
__global__ __launch_bounds__(512) void build_w_kernel(const int* __restrict__ indices,
                                                      const float* __restrict__ lut)
{
    __shared__ float lsh[16];
    __shared__ float ash[RANK];
    const int o = blockIdx.x;
    const int tid = threadIdx.x;
    if (tid < 16) lsh[tid] = lut[tid];
    if (tid < RANK) ash[tid] = g_aScaled[o * RANK + tid];
    __syncthreads();

    const float a0 = ash[0], a1 = ash[1], a2 = ash[2], a3 = ash[3];
    const int i0 = tid * 4;
    const int4 idx = *(const int4*)&indices[(size_t)o * IN_K + i0];
    const float4 b0 = *(const float4*)&g_bScaled[0 * IN_K + i0];
    const float4 b1 = *(const float4*)&g_bScaled[1 * IN_K + i0];
    const float4 b2 = *(const float4*)&g_bScaled[2 * IN_K + i0];
    const float4 b3 = *(const float4*)&g_bScaled[3 * IN_K + i0];

    float4 w;
    w.x = tf32r(lsh[idx.x] * (a0 * b0.x + a1 * b1.x + a2 * b2.x + a3 * b3.x));
    w.y = tf32r(lsh[idx.y] * (a0 * b0.y + a1 * b1.y + a2 * b2.y + a3 * b3.y));
    w.z = tf32r(lsh[idx.z] * (a0 * b0.z + a1 * b1.z + a2 * b2.z + a3 * b3.z));
    w.w = tf32r(lsh[idx.w] * (a0 * b0.w + a1 * b1.w + a2 * b2.w + a3 * b3.w));
    *(float4*)&g_W[(size_t)o * IN_K + i0] = w;
}

// ---------------- Kernel 3: X -> round-to-nearest tf32 ----------------------
__global__ __launch_bounds__(256) void round_x_kernel(const float* __restrict__ x)
{
    size_t i = ((size_t)blockIdx.x * 256 + threadIdx.x) * 4;
    float4 v = *(const float4*)&x[i];
    v.x = tf32r(v.x); v.y = tf32r(v.y); v.z = tf32r(v.z); v.w = tf32r(v.w);
    *(float4*)&g_X[i] = v;
}

// ---------------- Kernel 4: tf32 mma.sync GEMM ------------------------------
// Y[M,N] = X[M,K] * W[N,K]^T + bias ; CTA tile 128x256, BK=32, 3 stages.
#define BM 128
#define BN 256
#define BK 32
#define PADK 36                       // floats per smem row (32 + 4 pad)
#define STG_FLOATS ((BM + BN) * PADK) // 13824 floats per stage
#define AS_OFF 0
#define BS_OFF (BM * PADK)            // 4608
#define NKT (IN_K / BK)               // 64
#define DYN_SMEM (3 * STG_FLOATS * 4) // 165,888 B

__device__ __forceinline__ void cp16(void* dst, const void* src) {
    uint32_t d;
    asm("{ .reg .u64 t; cvta.to.shared.u64 t, %1; cvt.u32.u64 %0, t; }" : "=r"(d) : "l"(dst));
    asm volatile("cp.async.cg.shared.global [%0], [%1], 16;" :: "r"(d), "l"(src));
}
__device__ __forceinline__ void cp_commit() {
    asm volatile("cp.async.commit_group;" ::: "memory");
}
template<int N>
__device__ __forceinline__ void cp_wait() {
    asm volatile("cp.async.wait_group %0;" :: "n"(N) : "memory");
}
__device__ __forceinline__ void mma8(float& c0, float& c1, float& c2, float& c3,
                                     uint32_t a0, uint32_t a1, uint32_t a2, uint32_t a3,
                                     uint32_t b0, uint32_t b1) {
    asm volatile(
        "mma.sync.aligned.m16n8k8.row.col.f32.tf32.tf32.f32 "
        "{%0,%1,%2,%3}, {%4,%5,%6,%7}, {%8,%9}, {%0,%1,%2,%3};"
        : "+f"(c0), "+f"(c1), "+f"(c2), "+f"(c3)
        : "r"(a0), "r"(a1), "r"(a2), "r"(a3), "r"(b0), "r"(b1));
}

__global__ __launch_bounds__(256, 1) void gemm_kernel(const float* __restrict__ bias,
                                                      float* __restrict__ Y)
{
    extern __shared__ float smem[];
    const int tid = threadIdx.x;
    const int wid = tid >> 5, lane = tid & 31;
    const int warp_m = wid & 1, warp_n = wid >> 1;   // 2 x 4 warps
    const int gid = lane >> 2, tig = lane & 3;
    const int bm = blockIdx.y * BM;
    const int bn = blockIdx.x * BN;

    const float* Ag = g_X + (size_t)bm * IN_K;
    const float* Bg = g_W + (size_t)bn * IN_K;

    // load mapping: A 1024 float4 chunks (4/thread), B 2048 (8/thread)
    // chunk c: row = c>>3, kc = (c&7)*4
    float acc[4][8][4];
#pragma unroll
    for (int i = 0; i < 4; ++i)
#pragma unroll
        for (int j = 0; j < 8; ++j)
#pragma unroll
            for (int q = 0; q < 4; ++q) acc[i][j][q] = 0.f;

    // ---- prologue: stages 0,1 ----
#pragma unroll
    for (int s = 0; s < 2; ++s) {
        float* as = smem + s * STG_FLOATS + AS_OFF;
        float* bs = smem + s * STG_FLOATS + BS_OFF;
        const int kbase = s * BK;
#pragma unroll
        for (int i = 0; i < 4; ++i) {
            int c = tid + i * 256, row = c >> 3, kc = (c & 7) << 2;
            cp16(as + row * PADK + kc, Ag + (size_t)row * IN_K + kbase + kc);
        }
#pragma unroll
        for (int i = 0; i < 8; ++i) {
            int c = tid + i * 256, row = c >> 3, kc = (c & 7) << 2;
            cp16(bs + row * PADK + kc, Bg + (size_t)row * IN_K + kbase + kc);
        }
        cp_commit();
    }

    const int a_row0 = warp_m * 64 + gid;
    const int b_row0 = warp_n * 64 + gid;

    for (int kt = 0; kt < NKT; ++kt) {
        cp_wait<1>();
        __syncthreads();

        const int s = kt % 3;
        const float* a_base = smem + s * STG_FLOATS + AS_OFF + a_row0 * PADK + tig;
        const float* b_base = smem + s * STG_FLOATS + BS_OFF + b_row0 * PADK + tig;

#pragma unroll
        for (int ks = 0; ks < 4; ++ks) {
            const int k0 = ks * 8;
            uint32_t a[4][4];
#pragma unroll
            for (int mt = 0; mt < 4; ++mt) {
                a[mt][0] = __float_as_uint(a_base[(mt * 16) * PADK + k0]);
                a[mt][1] = __float_as_uint(a_base[(mt * 16 + 8) * PADK + k0]);
                a[mt][2] = __float_as_uint(a_base[(mt * 16) * PADK + k0 + 4]);
                a[mt][3] = __float_as_uint(a_base[(mt * 16 + 8) * PADK + k0 + 4]);
            }
            uint32_t b[8][2];
#pragma unroll
            for (int nt = 0; nt < 8; ++nt) {
                b[nt][0] = __float_as_uint(b_base[(nt * 8) * PADK + k0]);
                b[nt][1] = __float_as_uint(b_base[(nt * 8) * PADK + k0 + 4]);
            }
#pragma unroll
            for (int mt = 0; mt < 4; ++mt)
#pragma unroll
                for (int nt = 0; nt < 8; ++nt)
                    mma8(acc[mt][nt][0], acc[mt][nt][1], acc[mt][nt][2], acc[mt][nt][3],
                         a[mt][0], a[mt][1], a[mt][2], a[mt][3], b[nt][0], b[nt][1]);
        }

        __syncthreads();   // all warps done reading stage (kt)%3 before it is refilled

        const int ldk = kt + 2;
        if (ldk < NKT) {
            const int sn = ldk % 3;
            float* as = smem + sn * STG_FLOATS + AS_OFF;
            float* bs = smem + sn * STG_FLOATS + BS_OFF;
            const int kbase = ldk * BK;
#pragma unroll
            for (int i = 0; i < 4; ++i) {
                int c = tid + i * 256, row = c >> 3, kc = (c & 7) << 2;
                cp16(as + row * PADK + kc, Ag + (size_t)row * IN_K + kbase + kc);
            }
#pragma unroll
            for (int i = 0; i < 8; ++i) {
                int c = tid + i * 256, row = c >> 3, kc = (c & 7) << 2;
                cp16(bs + row * PADK + kc, Bg + (size_t)row * IN_K + kbase + kc);
            }
        }
        cp_commit();   // unconditional: keeps group accounting uniform
    }

    // ---- epilogue: bias + store ----
#pragma unroll
    for (int mt = 0; mt < 4; ++mt) {
        const int row0 = bm + warp_m * 64 + mt * 16 + gid;
#pragma unroll
        for (int nt = 0; nt < 8; ++nt) {
            const int col = bn + warp_n * 64 + nt * 8 + tig * 2;
            const float bx = __ldg(&bias[col]);
            const float by = __ldg(&bias[col + 1]);
            float2 v0 = make_float2(acc[mt][nt][0] + bx, acc[mt][nt][1] + by);
            float2 v1 = make_float2(acc[mt][nt][2] + bx, acc[mt][nt][3] + by);
            *(float2*)&Y[(size_t)row0 * OUT_N + col] = v0;
            *(float2*)&Y[(size_t)(row0 + 8) * OUT_N + col] = v1;
        }
    }
}

// ---------------- launch ----------------------------------------------------
extern "C" void kernel_launch(void* const* d_in, const int* in_sizes, int n_in,
                              void* d_out, int out_size)
{
    const float* x       = (const float*)d_in[0];  // [4, 2048, 2048]
    const int*   indices = (const int*)  d_in[1];  // [2048, 2048]
    const float* lut     = (const float*)d_in[2];  // [16]
    const float* sA      = (const float*)d_in[3];  // [2048, 4]
    const float* sB      = (const float*)d_in[4];  // [4, 2048]
    const float* mag     = (const float*)d_in[5];  // [4]
    const float* bias    = (const float*)d_in[6];  // [2048]
    float* y = (float*)d_out;                      // [4, 2048, 2048]

    cudaFuncSetAttribute(gemm_kernel, cudaFuncAttributeMaxDynamicSharedMemorySize, DYN_SMEM);

    round_x_kernel<<<(M_ROWS * IN_K) / (256 * 4), 256>>>(x);
    prep_kernel<<<1, 256>>>(sA, sB, mag);
    build_w_kernel<<<OUT_N, 512>>>(indices, lut);

    dim3 grid(OUT_N / BN, M_ROWS / BM);  // (8, 64)
    gemm_kernel<<<grid, 256, DYN_SMEM>>>(bias, y);
}

// round 4
// speedup vs baseline: 2.8915x; 1.0067x over previous
#include <cuda_runtime.h>
#include <math.h>
#include <stdint.h>

#define OUT_N  2048
#define IN_K   2048
#define M_ROWS 8192
#define RANK   4

// ---------------- scratch (static device globals; no runtime alloc) --------
__device__ float g_aScaled[OUT_N * RANK];
__device__ float g_bScaled[RANK * IN_K];
__device__ float g_W[(size_t)OUT_N * IN_K];   // tf32-rounded effective weight
__device__ float g_X[(size_t)M_ROWS * IN_K];  // tf32-rounded activations

__device__ __forceinline__ float tf32r(float x) {
    float y;
    asm("cvt.rna.tf32.f32 %0, %1;" : "=f"(y) : "f"(x));
    return y;
}

// ---------------- Kernel 1: rank norms + softplus (warp per rank) -----------
__global__ __launch_bounds__(256) void prep_kernel(const float* __restrict__ sA,
                                                   const float* __restrict__ sB,
                                                   const float* __restrict__ mag)
{
    __shared__ float cA[RANK], cB[RANK];
    const int tid = threadIdx.x, wid = tid >> 5, lid = tid & 31;
    if (wid < 4) {
        const int r = wid;
        float s = 0.f;
        for (int o = lid; o < OUT_N; o += 32) { float v = sA[o * RANK + r]; s += v * v; }
        for (int off = 16; off; off >>= 1) s += __shfl_xor_sync(0xffffffff, s, off);
        if (lid == 0) {
            float nrm = fmaxf(sqrtf(s), 1e-6f);
            float m = mag[r];
            float g = (m > 20.f ? m : log1pf(expf(m))) + 1e-6f;
            cA[r] = g / nrm;
        }
    } else {
        const int r = wid - 4;
        float s = 0.f;
        for (int i = lid; i < IN_K; i += 32) { float v = sB[r * IN_K + i]; s += v * v; }
        for (int off = 16; off; off >>= 1) s += __shfl_xor_sync(0xffffffff, s, off);
        if (lid == 0) cB[r] = 1.f / fmaxf(sqrtf(s), 1e-6f);
    }
    __syncthreads();
    for (int idx = tid; idx < OUT_N * RANK; idx += 256)
        g_aScaled[idx] = fabsf(sA[idx]) * cA[idx & 3];
    for (int idx = tid; idx < RANK * IN_K; idx += 256)
        g_bScaled[idx] = fabsf(sB[idx]) * cB[idx >> 11];
}

// ---------------- Kernel 2: W = round_tf32(lut[idx] * dot4(a,b)) ------------
__global__ __launch_bounds__(512) void build_w_kernel(const int* __restrict__ indices,
                                                      const float* __restrict__ lut)
{
    __shared__ float lsh[16];
    __shared__ float ash[RANK];
    const int o = blockIdx.x;
    const int tid = threadIdx.x;
    if (tid < 16) lsh[tid] = lut[tid];
    if (tid < RANK) ash[tid] = g_aScaled[o * RANK + tid];
    __syncthreads();

    const float a0 = ash[0], a1 = ash[1], a2 = ash[2], a3 = ash[3];
    const int i0 = tid * 4;
    const int4 idx = *(const int4*)&indices[(size_t)o * IN_K + i0];
    const float4 b0 = *(const float4*)&g_bScaled[0 * IN_K + i0];
    const float4 b1 = *(const float4*)&g_bScaled[1 * IN_K + i0];
    const float4 b2 = *(const float4*)&g_bScaled[2 * IN_K + i0];
    const float4 b3 = *(const float4*)&g_bScaled[3 * IN_K + i0];

    float4 w;
    w.x = tf32r(lsh[idx.x] * (a0 * b0.x + a1 * b1.x + a2 * b2.x + a3 * b3.x));
    w.y = tf32r(lsh[idx.y] * (a0 * b0.y + a1 * b1.y + a2 * b2.y + a3 * b3.y));
    w.z = tf32r(lsh[idx.z] * (a0 * b0.z + a1 * b1.z + a2 * b2.z + a3 * b3.z));
    w.w = tf32r(lsh[idx.w] * (a0 * b0.w + a1 * b1.w + a2 * b2.w + a3 * b3.w));
    *(float4*)&g_W[(size_t)o * IN_K + i0] = w;
}

// ---------------- Kernel 3: X -> round-to-nearest tf32 ----------------------
__global__ __launch_bounds__(256) void round_x_kernel(const float* __restrict__ x)
{
    size_t i = ((size_t)blockIdx.x * 256 + threadIdx.x) * 4;
    float4 v = *(const float4*)&x[i];
    v.x = tf32r(v.x); v.y = tf32r(v.y); v.z = tf32r(v.z); v.w = tf32r(v.w);
    *(float4*)&g_X[i] = v;
}

// ---------------- Kernel 4: tf32 mma.sync GEMM ------------------------------
// Y[M,N] = X[M,K] * W[N,K]^T + bias ; CTA tile 128x256, BK=32, 4 stages,
// single barrier per k-iter, loads issued before compute.
#define BM 128
#define BN 256
#define BK 32
#define PADK 36                       // floats per smem row (32 + 4 pad)
#define STG_FLOATS ((BM + BN) * PADK) // 13824 floats per stage
#define AS_OFF 0
#define BS_OFF (BM * PADK)            // 4608
#define NKT (IN_K / BK)               // 64
#define NSTG 4
#define DYN_SMEM (NSTG * STG_FLOATS * 4) // 221,184 B

__device__ __forceinline__ void cp16(void* dst, const void* src) {
    uint32_t d;
    asm("{ .reg .u64 t; cvta.to.shared.u64 t, %1; cvt.u32.u64 %0, t; }" : "=r"(d) : "l"(dst));
    asm volatile("cp.async.cg.shared.global [%0], [%1], 16;" :: "r"(d), "l"(src));
}
__device__ __forceinline__ void cp_commit() {
    asm volatile("cp.async.commit_group;" ::: "memory");
}
template<int N>
__device__ __forceinline__ void cp_wait() {
    asm volatile("cp.async.wait_group %0;" :: "n"(N) : "memory");
}
__device__ __forceinline__ void mma8(float& c0, float& c1, float& c2, float& c3,
                                     uint32_t a0, uint32_t a1, uint32_t a2, uint32_t a3,
                                     uint32_t b0, uint32_t b1) {
    asm volatile(
        "mma.sync.aligned.m16n8k8.row.col.f32.tf32.tf32.f32 "
        "{%0,%1,%2,%3}, {%4,%5,%6,%7}, {%8,%9}, {%0,%1,%2,%3};"
        : "+f"(c0), "+f"(c1), "+f"(c2), "+f"(c3)
        : "r"(a0), "r"(a1), "r"(a2), "r"(a3), "r"(b0), "r"(b1));
}

__device__ __forceinline__ void issue_stage(float* smem, int stage, int kbase,
                                            const float* Ag, const float* Bg, int tid)
{
    float* as = smem + stage * STG_FLOATS + AS_OFF;
    float* bs = smem + stage * STG_FLOATS + BS_OFF;
#pragma unroll
    for (int i = 0; i < 4; ++i) {
        int c = tid + i * 256, row = c >> 3, kc = (c & 7) << 2;
        cp16(as + row * PADK + kc, Ag + (size_t)row * IN_K + kbase + kc);
    }
#pragma unroll
    for (int i = 0; i < 8; ++i) {
        int c = tid + i * 256, row = c >> 3, kc = (c & 7) << 2;
        cp16(bs + row * PADK + kc, Bg + (size_t)row * IN_K + kbase + kc);
    }
    cp_commit();
}

__global__ __launch_bounds__(256, 1) void gemm_kernel(const float* __restrict__ bias,
                                                      float* __restrict__ Y)
{
    extern __shared__ float smem[];
    const int tid = threadIdx.x;
    const int wid = tid >> 5, lane = tid & 31;
    const int warp_m = wid & 1, warp_n = wid >> 1;   // 2 x 4 warps
    const int gid = lane >> 2, tig = lane & 3;
    const int bm = blockIdx.y * BM;
    const int bn = blockIdx.x * BN;

    const float* Ag = g_X + (size_t)bm * IN_K;
    const float* Bg = g_W + (size_t)bn * IN_K;

    float acc[4][8][4];
#pragma unroll
    for (int i = 0; i < 4; ++i)
#pragma unroll
        for (int j = 0; j < 8; ++j)
#pragma unroll
            for (int q = 0; q < 4; ++q) acc[i][j][q] = 0.f;

    // ---- prologue: stages 0,1,2 ----
    issue_stage(smem, 0, 0 * BK, Ag, Bg, tid);
    issue_stage(smem, 1, 1 * BK, Ag, Bg, tid);
    issue_stage(smem, 2, 2 * BK, Ag, Bg, tid);

    const int a_row0 = warp_m * 64 + gid;
    const int b_row0 = warp_n * 64 + gid;

    for (int kt = 0; kt < NKT; ++kt) {
        cp_wait<2>();          // stage kt%NSTG data resident
        __syncthreads();       // all warps done computing kt-1 -> stage (kt+3)%4 free

        const int ldk = kt + 3;
        if (ldk < NKT)
            issue_stage(smem, ldk % NSTG, ldk * BK, Ag, Bg, tid);

        const int s = kt % NSTG;
        const float* a_base = smem + s * STG_FLOATS + AS_OFF + a_row0 * PADK + tig;
        const float* b_base = smem + s * STG_FLOATS + BS_OFF + b_row0 * PADK + tig;

#pragma unroll
        for (int ks = 0; ks < 4; ++ks) {
            const int k0 = ks * 8;
            uint32_t a[4][4];
#pragma unroll
            for (int mt = 0; mt < 4; ++mt) {
                a[mt][0] = __float_as_uint(a_base[(mt * 16) * PADK + k0]);
                a[mt][1] = __float_as_uint(a_base[(mt * 16 + 8) * PADK + k0]);
                a[mt][2] = __float_as_uint(a_base[(mt * 16) * PADK + k0 + 4]);
                a[mt][3] = __float_as_uint(a_base[(mt * 16 + 8) * PADK + k0 + 4]);
            }
            uint32_t b[8][2];
#pragma unroll
            for (int nt = 0; nt < 8; ++nt) {
                b[nt][0] = __float_as_uint(b_base[(nt * 8) * PADK + k0]);
                b[nt][1] = __float_as_uint(b_base[(nt * 8) * PADK + k0 + 4]);
            }
#pragma unroll
            for (int mt = 0; mt < 4; ++mt)
#pragma unroll
                for (int nt = 0; nt < 8; ++nt)
                    mma8(acc[mt][nt][0], acc[mt][nt][1], acc[mt][nt][2], acc[mt][nt][3],
                         a[mt][0], a[mt][1], a[mt][2], a[mt][3], b[nt][0], b[nt][1]);
        }
    }

    // ---- epilogue: bias + store ----
#pragma unroll
    for (int mt = 0; mt < 4; ++mt) {
        const int row0 = bm + warp_m * 64 + mt * 16 + gid;
#pragma unroll
        for (int nt = 0; nt < 8; ++nt) {
            const int col = bn + warp_n * 64 + nt * 8 + tig * 2;
            const float bx = __ldg(&bias[col]);
            const float by = __ldg(&bias[col + 1]);
            float2 v0 = make_float2(acc[mt][nt][0] + bx, acc[mt][nt][1] + by);
            float2 v1 = make_float2(acc[mt][nt][2] + bx, acc[mt][nt][3] + by);
            *(float2*)&Y[(size_t)row0 * OUT_N + col] = v0;
            *(float2*)&Y[(size_t)(row0 + 8) * OUT_N + col] = v1;
        }
    }
}

// ---------------- launch ----------------------------------------------------
extern "C" void kernel_launch(void* const* d_in, const int* in_sizes, int n_in,
                              void* d_out, int out_size)
{
    const float* x       = (const float*)d_in[0];  // [4, 2048, 2048]
    const int*   indices = (const int*)  d_in[1];  // [2048, 2048]
    const float* lut     = (const float*)d_in[2];  // [16]
    const float* sA      = (const float*)d_in[3];  // [2048, 4]
    const float* sB      = (const float*)d_in[4];  // [4, 2048]
    const float* mag     = (const float*)d_in[5];  // [4]
    const float* bias    = (const float*)d_in[6];  // [2048]
    float* y = (float*)d_out;                      // [4, 2048, 2048]

    cudaFuncSetAttribute(gemm_kernel, cudaFuncAttributeMaxDynamicSharedMemorySize, DYN_SMEM);

    round_x_kernel<<<(M_ROWS * IN_K) / (256 * 4), 256>>>(x);
    prep_kernel<<<1, 256>>>(sA, sB, mag);
    build_w_kernel<<<OUT_N, 512>>>(indices, lut);

    dim3 grid(OUT_N / BN, M_ROWS / BM);  // (8, 64)
    gemm_kernel<<<grid, 256, DYN_SMEM>>>(bias, y);
}

// round 5
// speedup vs baseline: 3.1901x; 1.1033x over previous
#include <cuda_runtime.h>
#include <math.h>
#include <stdint.h>

#define OUT_N  2048
#define IN_K   2048
#define M_ROWS 8192
#define RANK   4

// ---------------- scratch (static device globals; no runtime alloc) --------
__device__ float g_aScaled[OUT_N * RANK];
__device__ float g_bScaled[RANK * IN_K];
__device__ float g_W[(size_t)OUT_N * IN_K];   // tf32-rounded effective weight
__device__ float g_X[(size_t)M_ROWS * IN_K];  // tf32-rounded activations

__device__ __forceinline__ float tf32r(float x) {
    float y;
    asm("cvt.rna.tf32.f32 %0, %1;" : "=f"(y) : "f"(x));
    return y;
}

// ---------------- Kernel 1: rank norms + softplus (warp per rank) -----------
__global__ __launch_bounds__(256) void prep_kernel(const float* __restrict__ sA,
                                                   const float* __restrict__ sB,
                                                   const float* __restrict__ mag)
{
    __shared__ float cA[RANK], cB[RANK];
    const int tid = threadIdx.x, wid = tid >> 5, lid = tid & 31;
    if (wid < 4) {
        const int r = wid;
        float s = 0.f;
        for (int o = lid; o < OUT_N; o += 32) { float v = sA[o * RANK + r]; s += v * v; }
        for (int off = 16; off; off >>= 1) s += __shfl_xor_sync(0xffffffff, s, off);
        if (lid == 0) {
            float nrm = fmaxf(sqrtf(s), 1e-6f);
            float m = mag[r];
            float g = (m > 20.f ? m : log1pf(expf(m))) + 1e-6f;
            cA[r] = g / nrm;
        }
    } else {
        const int r = wid - 4;
        float s = 0.f;
        for (int i = lid; i < IN_K; i += 32) { float v = sB[r * IN_K + i]; s += v * v; }
        for (int off = 16; off; off >>= 1) s += __shfl_xor_sync(0xffffffff, s, off);
        if (lid == 0) cB[r] = 1.f / fmaxf(sqrtf(s), 1e-6f);
    }
    __syncthreads();
    for (int idx = tid; idx < OUT_N * RANK; idx += 256)
        g_aScaled[idx] = fabsf(sA[idx]) * cA[idx & 3];
    for (int idx = tid; idx < RANK * IN_K; idx += 256)
        g_bScaled[idx] = fabsf(sB[idx]) * cB[idx >> 11];
}

// ---------------- Kernel 2: W = round_tf32(lut[idx] * dot4(a,b)) ------------
__global__ __launch_bounds__(512) void build_w_kernel(const int* __restrict__ indices,
                                                      const float* __restrict__ lut)
{
    __shared__ float lsh[16];
    __shared__ float ash[RANK];
    const int o = blockIdx.x;
    const int tid = threadIdx.x;
    if (tid < 16) lsh[tid] = lut[tid];
    if (tid < RANK) ash[tid] = g_aScaled[o * RANK + tid];
    __syncthreads();

    const float a0 = ash[0], a1 = ash[1], a2 = ash[2], a3 = ash[3];
    const int i0 = tid * 4;
    const int4 idx = *(const int4*)&indices[(size_t)o * IN_K + i0];
    const float4 b0 = *(const float4*)&g_bScaled[0 * IN_K + i0];
    const float4 b1 = *(const float4*)&g_bScaled[1 * IN_K + i0];
    const float4 b2 = *(const float4*)&g_bScaled[2 * IN_K + i0];
    const float4 b3 = *(const float4*)&g_bScaled[3 * IN_K + i0];

    float4 w;
    w.x = tf32r(lsh[idx.x] * (a0 * b0.x + a1 * b1.x + a2 * b2.x + a3 * b3.x));
    w.y = tf32r(lsh[idx.y] * (a0 * b0.y + a1 * b1.y + a2 * b2.y + a3 * b3.y));
    w.z = tf32r(lsh[idx.z] * (a0 * b0.z + a1 * b1.z + a2 * b2.z + a3 * b3.z));
    w.w = tf32r(lsh[idx.w] * (a0 * b0.w + a1 * b1.w + a2 * b2.w + a3 * b3.w));
    *(float4*)&g_W[(size_t)o * IN_K + i0] = w;
}

// ---------------- Kernel 3: X -> round-to-nearest tf32 ----------------------
__global__ __launch_bounds__(256) void round_x_kernel(const float* __restrict__ x)
{
    size_t i = ((size_t)blockIdx.x * 256 + threadIdx.x) * 4;
    float4 v = *(const float4*)&x[i];
    v.x = tf32r(v.x); v.y = tf32r(v.y); v.z = tf32r(v.z); v.w = tf32r(v.w);
    *(float4*)&g_X[i] = v;
}

// ---------------- Kernel 4: tf32 mma.sync GEMM ------------------------------
// Y[M,N] = X[M,K] * W[N,K]^T + bias ; CTA tile 128x128, BK=32, 3 stages,
// 2 CTAs/SM (4 warps/SMSP) for latency hiding.
#define BM 128
#define BN 128
#define BK 32
#define PADK 36                       // floats per smem row (32 + 4 pad)
#define STG_FLOATS ((BM + BN) * PADK) // 9216 floats per stage
#define AS_OFF 0
#define BS_OFF (BM * PADK)            // 4608
#define NKT (IN_K / BK)               // 64
#define NSTG 3
#define DYN_SMEM (NSTG * STG_FLOATS * 4) // 110,592 B

__device__ __forceinline__ void cp16(void* dst, const void* src) {
    uint32_t d;
    asm("{ .reg .u64 t; cvta.to.shared.u64 t, %1; cvt.u32.u64 %0, t; }" : "=r"(d) : "l"(dst));
    asm volatile("cp.async.cg.shared.global [%0], [%1], 16;" :: "r"(d), "l"(src));
}
__device__ __forceinline__ void cp_commit() {
    asm volatile("cp.async.commit_group;" ::: "memory");
}
template<int N>
__device__ __forceinline__ void cp_wait() {
    asm volatile("cp.async.wait_group %0;" :: "n"(N) : "memory");
}
__device__ __forceinline__ void mma8(float& c0, float& c1, float& c2, float& c3,
                                     uint32_t a0, uint32_t a1, uint32_t a2, uint32_t a3,
                                     uint32_t b0, uint32_t b1) {
    asm volatile(
        "mma.sync.aligned.m16n8k8.row.col.f32.tf32.tf32.f32 "
        "{%0,%1,%2,%3}, {%4,%5,%6,%7}, {%8,%9}, {%0,%1,%2,%3};"
        : "+f"(c0), "+f"(c1), "+f"(c2), "+f"(c3)
        : "r"(a0), "r"(a1), "r"(a2), "r"(a3), "r"(b0), "r"(b1));
}

__device__ __forceinline__ void issue_stage(float* smem, int stage, int kbase,
                                            const float* Ag, const float* Bg, int tid)
{
    float* as = smem + stage * STG_FLOATS + AS_OFF;
    float* bs = smem + stage * STG_FLOATS + BS_OFF;
    // 128 rows x 8 chunks = 1024 chunks each for A and B; 4 per thread
#pragma unroll
    for (int i = 0; i < 4; ++i) {
        int c = tid + i * 256, row = c >> 3, kc = (c & 7) << 2;
        cp16(as + row * PADK + kc, Ag + (size_t)row * IN_K + kbase + kc);
    }
#pragma unroll
    for (int i = 0; i < 4; ++i) {
        int c = tid + i * 256, row = c >> 3, kc = (c & 7) << 2;
        cp16(bs + row * PADK + kc, Bg + (size_t)row * IN_K + kbase + kc);
    }
    cp_commit();
}

__global__ __launch_bounds__(256, 2) void gemm_kernel(const float* __restrict__ bias,
                                                      float* __restrict__ Y)
{
    extern __shared__ float smem[];
    const int tid = threadIdx.x;
    const int wid = tid >> 5, lane = tid & 31;
    const int warp_m = wid & 1, warp_n = wid >> 1;   // 2 x 4 warps; warp tile 64x32
    const int gid = lane >> 2, tig = lane & 3;
    const int bm = blockIdx.y * BM;
    const int bn = blockIdx.x * BN;

    const float* Ag = g_X + (size_t)bm * IN_K;
    const float* Bg = g_W + (size_t)bn * IN_K;

    float acc[4][4][4];
#pragma unroll
    for (int i = 0; i < 4; ++i)
#pragma unroll
        for (int j = 0; j < 4; ++j)
#pragma unroll
            for (int q = 0; q < 4; ++q) acc[i][j][q] = 0.f;

    // ---- prologue: stages 0,1 ----
    issue_stage(smem, 0, 0 * BK, Ag, Bg, tid);
    issue_stage(smem, 1, 1 * BK, Ag, Bg, tid);

    const int a_row0 = warp_m * 64 + gid;
    const int b_row0 = warp_n * 32 + gid;

    for (int kt = 0; kt < NKT; ++kt) {
        cp_wait<1>();          // stage kt%3 resident
        __syncthreads();       // compute of kt-1 done -> stage (kt+2)%3 free

        const int ldk = kt + 2;
        if (ldk < NKT)
            issue_stage(smem, ldk % NSTG, ldk * BK, Ag, Bg, tid);

        const int s = kt % NSTG;
        const float* a_base = smem + s * STG_FLOATS + AS_OFF + a_row0 * PADK + tig;
        const float* b_base = smem + s * STG_FLOATS + BS_OFF + b_row0 * PADK + tig;

#pragma unroll
        for (int ks = 0; ks < 4; ++ks) {
            const int k0 = ks * 8;
            uint32_t a[4][4];
#pragma unroll
            for (int mt = 0; mt < 4; ++mt) {
                a[mt][0] = __float_as_uint(a_base[(mt * 16) * PADK + k0]);
                a[mt][1] = __float_as_uint(a_base[(mt * 16 + 8) * PADK + k0]);
                a[mt][2] = __float_as_uint(a_base[(mt * 16) * PADK + k0 + 4]);
                a[mt][3] = __float_as_uint(a_base[(mt * 16 + 8) * PADK + k0 + 4]);
            }
            uint32_t b[4][2];
#pragma unroll
            for (int nt = 0; nt < 4; ++nt) {
                b[nt][0] = __float_as_uint(b_base[(nt * 8) * PADK + k0]);
                b[nt][1] = __float_as_uint(b_base[(nt * 8) * PADK + k0 + 4]);
            }
#pragma unroll
            for (int mt = 0; mt < 4; ++mt)
#pragma unroll
                for (int nt = 0; nt < 4; ++nt)
                    mma8(acc[mt][nt][0], acc[mt][nt][1], acc[mt][nt][2], acc[mt][nt][3],
                         a[mt][0], a[mt][1], a[mt][2], a[mt][3], b[nt][0], b[nt][1]);
        }
    }

    // ---- epilogue: bias + store ----
#pragma unroll
    for (int mt = 0; mt < 4; ++mt) {
        const int row0 = bm + warp_m * 64 + mt * 16 + gid;
#pragma unroll
        for (int nt = 0; nt < 4; ++nt) {
            const int col = bn + warp_n * 32 + nt * 8 + tig * 2;
            const float bx = __ldg(&bias[col]);
            const float by = __ldg(&bias[col + 1]);
            float2 v0 = make_float2(acc[mt][nt][0] + bx, acc[mt][nt][1] + by);
            float2 v1 = make_float2(acc[mt][nt][2] + bx, acc[mt][nt][3] + by);
            *(float2*)&Y[(size_t)row0 * OUT_N + col] = v0;
            *(float2*)&Y[(size_t)(row0 + 8) * OUT_N + col] = v1;
        }
    }
}

// ---------------- launch ----------------------------------------------------
extern "C" void kernel_launch(void* const* d_in, const int* in_sizes, int n_in,
                              void* d_out, int out_size)
{
    const float* x       = (const float*)d_in[0];  // [4, 2048, 2048]
    const int*   indices = (const int*)  d_in[1];  // [2048, 2048]
    const float* lut     = (const float*)d_in[2];  // [16]
    const float* sA      = (const float*)d_in[3];  // [2048, 4]
    const float* sB      = (const float*)d_in[4];  // [4, 2048]
    const float* mag     = (const float*)d_in[5];  // [4]
    const float* bias    = (const float*)d_in[6];  // [2048]
    float* y = (float*)d_out;                      // [4, 2048, 2048]

    cudaFuncSetAttribute(gemm_kernel, cudaFuncAttributeMaxDynamicSharedMemorySize, DYN_SMEM);

    round_x_kernel<<<(M_ROWS * IN_K) / (256 * 4), 256>>>(x);
    prep_kernel<<<1, 256>>>(sA, sB, mag);
    build_w_kernel<<<OUT_N, 512>>>(indices, lut);

    dim3 grid(OUT_N / BN, M_ROWS / BM);  // (16, 64)
    gemm_kernel<<<grid, 256, DYN_SMEM>>>(bias, y);
}

// round 7
// speedup vs baseline: 5.7154x; 1.7916x over previous
#include <cuda_runtime.h>
#include <cuda_fp16.h>
#include <math.h>
#include <stdint.h>

#define OUT_N  2048
#define IN_K   2048
#define M_ROWS 8192
#define RANK   4

// ---------------- scratch (static device globals; no runtime alloc) --------
__device__ float  g_aScaled[OUT_N * RANK];
__device__ float  g_bScaled[RANK * IN_K];
__device__ __half g_W[(size_t)OUT_N * IN_K];   // fp16 effective weight (8 MB)
__device__ __half g_X[(size_t)M_ROWS * IN_K];  // fp16 activations (32 MB)

__device__ __forceinline__ uint32_t h2_bits(__half2 h) {
    union { __half2 h; uint32_t u; } cvt;
    cvt.h = h;
    return cvt.u;
}

// ---------------- Kernel 1: rank norms + softplus (warp per rank) -----------
__global__ __launch_bounds__(256) void prep_kernel(const float* __restrict__ sA,
                                                   const float* __restrict__ sB,
                                                   const float* __restrict__ mag)
{
    __shared__ float cA[RANK], cB[RANK];
    const int tid = threadIdx.x, wid = tid >> 5, lid = tid & 31;
    if (wid < 4) {
        const int r = wid;
        float s = 0.f;
        for (int o = lid; o < OUT_N; o += 32) { float v = sA[o * RANK + r]; s += v * v; }
        for (int off = 16; off; off >>= 1) s += __shfl_xor_sync(0xffffffff, s, off);
        if (lid == 0) {
            float nrm = fmaxf(sqrtf(s), 1e-6f);
            float m = mag[r];
            float g = (m > 20.f ? m : log1pf(expf(m))) + 1e-6f;
            cA[r] = g / nrm;
        }
    } else {
        const int r = wid - 4;
        float s = 0.f;
        for (int i = lid; i < IN_K; i += 32) { float v = sB[r * IN_K + i]; s += v * v; }
        for (int off = 16; off; off >>= 1) s += __shfl_xor_sync(0xffffffff, s, off);
        if (lid == 0) cB[r] = 1.f / fmaxf(sqrtf(s), 1e-6f);
    }
    __syncthreads();
    for (int idx = tid; idx < OUT_N * RANK; idx += 256)
        g_aScaled[idx] = fabsf(sA[idx]) * cA[idx & 3];
    for (int idx = tid; idx < RANK * IN_K; idx += 256)
        g_bScaled[idx] = fabsf(sB[idx]) * cB[idx >> 11];
}

// ---------------- Kernel 2: W = half(lut[idx] * dot4(a,b)) ------------------
__global__ __launch_bounds__(512) void build_w_kernel(const int* __restrict__ indices,
                                                      const float* __restrict__ lut)
{
    __shared__ float lsh[16];
    __shared__ float ash[RANK];
    const int o = blockIdx.x;
    const int tid = threadIdx.x;
    if (tid < 16) lsh[tid] = lut[tid];
    if (tid < RANK) ash[tid] = g_aScaled[o * RANK + tid];
    __syncthreads();

    const float a0 = ash[0], a1 = ash[1], a2 = ash[2], a3 = ash[3];
    const int i0 = tid * 4;
    const int4 idx = *(const int4*)&indices[(size_t)o * IN_K + i0];
    const float4 b0 = *(const float4*)&g_bScaled[0 * IN_K + i0];
    const float4 b1 = *(const float4*)&g_bScaled[1 * IN_K + i0];
    const float4 b2 = *(const float4*)&g_bScaled[2 * IN_K + i0];
    const float4 b3 = *(const float4*)&g_bScaled[3 * IN_K + i0];

    __half2 w01 = __floats2half2_rn(
        lsh[idx.x] * (a0 * b0.x + a1 * b1.x + a2 * b2.x + a3 * b3.x),
        lsh[idx.y] * (a0 * b0.y + a1 * b1.y + a2 * b2.y + a3 * b3.y));
    __half2 w23 = __floats2half2_rn(
        lsh[idx.z] * (a0 * b0.z + a1 * b1.z + a2 * b2.z + a3 * b3.z),
        lsh[idx.w] * (a0 * b0.w + a1 * b1.w + a2 * b2.w + a3 * b3.w));
    uint2 packed = make_uint2(h2_bits(w01), h2_bits(w23));
    *(uint2*)&g_W[(size_t)o * IN_K + i0] = packed;
}

// ---------------- Kernel 3: X -> fp16 ---------------------------------------
__global__ __launch_bounds__(256) void round_x_kernel(const float* __restrict__ x)
{
    size_t i = ((size_t)blockIdx.x * 256 + threadIdx.x) * 8;
    float4 v0 = *(const float4*)&x[i];
    float4 v1 = *(const float4*)&x[i + 4];
    uint4 out;
    out.x = h2_bits(__floats2half2_rn(v0.x, v0.y));
    out.y = h2_bits(__floats2half2_rn(v0.z, v0.w));
    out.z = h2_bits(__floats2half2_rn(v1.x, v1.y));
    out.w = h2_bits(__floats2half2_rn(v1.z, v1.w));
    *(uint4*)&g_X[i] = out;
}

// ---------------- Kernel 4: fp16 mma.sync GEMM ------------------------------
// Y[M,N] = X[M,K] * W[N,K]^T + bias ; CTA tile 128x128, BK=64 halves,
// 3 stages, 2 CTAs/SM, m16n8k16 f16 with fp32 accumulate.
#define BM 128
#define BN 128
#define BK 64
#define PADH 72                        // halves per smem row (64 + 8 pad = 144B)
#define STG_HALVES ((BM + BN) * PADH)  // 18432 halves per stage (36,864 B)
#define AS_OFF 0
#define BS_OFF (BM * PADH)             // 9216
#define NKT (IN_K / BK)                // 32
#define NSTG 3
#define DYN_SMEM (NSTG * STG_HALVES * 2) // 110,592 B

__device__ __forceinline__ void cp16(void* dst, const void* src) {
    uint32_t d;
    asm("{ .reg .u64 t; cvta.to.shared.u64 t, %1; cvt.u32.u64 %0, t; }" : "=r"(d) : "l"(dst));
    asm volatile("cp.async.cg.shared.global [%0], [%1], 16;" :: "r"(d), "l"(src));
}
__device__ __forceinline__ void cp_commit() {
    asm volatile("cp.async.commit_group;" ::: "memory");
}
template<int N>
__device__ __forceinline__ void cp_wait() {
    asm volatile("cp.async.wait_group %0;" :: "n"(N) : "memory");
}
__device__ __forceinline__ void mma16(float& c0, float& c1, float& c2, float& c3,
                                      uint32_t a0, uint32_t a1, uint32_t a2, uint32_t a3,
                                      uint32_t b0, uint32_t b1) {
    asm volatile(
        "mma.sync.aligned.m16n8k16.row.col.f32.f16.f16.f32 "
        "{%0,%1,%2,%3}, {%4,%5,%6,%7}, {%8,%9}, {%0,%1,%2,%3};"
        : "+f"(c0), "+f"(c1), "+f"(c2), "+f"(c3)
        : "r"(a0), "r"(a1), "r"(a2), "r"(a3), "r"(b0), "r"(b1));
}

__device__ __forceinline__ void issue_stage(__half* smem, int stage, int kbase,
                                            const __half* Ag, const __half* Bg, int tid)
{
    __half* as = smem + stage * STG_HALVES + AS_OFF;
    __half* bs = smem + stage * STG_HALVES + BS_OFF;
    // 128 rows x 8 chunks (16B = 8 halves) = 1024 chunks each; 4 per thread
#pragma unroll
    for (int i = 0; i < 4; ++i) {
        int c = tid + i * 256, row = c >> 3, kc = (c & 7) << 3;
        cp16(as + row * PADH + kc, Ag + (size_t)row * IN_K + kbase + kc);
    }
#pragma unroll
    for (int i = 0; i < 4; ++i) {
        int c = tid + i * 256, row = c >> 3, kc = (c & 7) << 3;
        cp16(bs + row * PADH + kc, Bg + (size_t)row * IN_K + kbase + kc);
    }
    cp_commit();
}

__global__ __launch_bounds__(256, 2) void gemm_kernel(const float* __restrict__ bias,
                                                      float* __restrict__ Y)
{
    extern __shared__ __half smem[];
    const int tid = threadIdx.x;
    const int wid = tid >> 5, lane = tid & 31;
    const int warp_m = wid & 1, warp_n = wid >> 1;   // 2 x 4 warps; warp tile 64x32
    const int gid = lane >> 2, tig = lane & 3;
    const int bm = blockIdx.y * BM;
    const int bn = blockIdx.x * BN;

    const __half* Ag = g_X + (size_t)bm * IN_K;
    const __half* Bg = g_W + (size_t)bn * IN_K;

    float acc[4][4][4];
#pragma unroll
    for (int i = 0; i < 4; ++i)
#pragma unroll
        for (int j = 0; j < 4; ++j)
#pragma unroll
            for (int q = 0; q < 4; ++q) acc[i][j][q] = 0.f;

    // ---- prologue: stages 0,1 ----
    issue_stage(smem, 0, 0 * BK, Ag, Bg, tid);
    issue_stage(smem, 1, 1 * BK, Ag, Bg, tid);

    const int a_row0 = warp_m * 64 + gid;
    const int b_row0 = warp_n * 32 + gid;

    for (int kt = 0; kt < NKT; ++kt) {
        cp_wait<1>();          // stage kt%3 resident
        __syncthreads();       // compute of kt-1 done -> stage (kt+2)%3 free

        const int ldk = kt + 2;
        if (ldk < NKT)
            issue_stage(smem, ldk % NSTG, ldk * BK, Ag, Bg, tid);

        const int s = kt % NSTG;
        const __half* a_base = smem + s * STG_HALVES + AS_OFF + a_row0 * PADH + tig * 2;
        const __half* b_base = smem + s * STG_HALVES + BS_OFF + b_row0 * PADH + tig * 2;

#pragma unroll
        for (int ks = 0; ks < 4; ++ks) {      // 4 x k16 per BK=64
            const int k0 = ks * 16;
            uint32_t a[4][4];
#pragma unroll
            for (int mt = 0; mt < 4; ++mt) {
                a[mt][0] = *(const uint32_t*)&a_base[(mt * 16) * PADH + k0];
                a[mt][1] = *(const uint32_t*)&a_base[(mt * 16 + 8) * PADH + k0];
                a[mt][2] = *(const uint32_t*)&a_base[(mt * 16) * PADH + k0 + 8];
                a[mt][3] = *(const uint32_t*)&a_base[(mt * 16 + 8) * PADH + k0 + 8];
            }
            uint32_t b[4][2];
#pragma unroll
            for (int nt = 0; nt < 4; ++nt) {
                b[nt][0] = *(const uint32_t*)&b_base[(nt * 8) * PADH + k0];
                b[nt][1] = *(const uint32_t*)&b_base[(nt * 8) * PADH + k0 + 8];
            }
#pragma unroll
            for (int mt = 0; mt < 4; ++mt)
#pragma unroll
                for (int nt = 0; nt < 4; ++nt)
                    mma16(acc[mt][nt][0], acc[mt][nt][1], acc[mt][nt][2], acc[mt][nt][3],
                          a[mt][0], a[mt][1], a[mt][2], a[mt][3], b[nt][0], b[nt][1]);
        }
    }

    // ---- epilogue: bias + store ----
#pragma unroll
    for (int mt = 0; mt < 4; ++mt) {
        const int row0 = bm + warp_m * 64 + mt * 16 + gid;
#pragma unroll
        for (int nt = 0; nt < 4; ++nt) {
            const int col = bn + warp_n * 32 + nt * 8 + tig * 2;
            const float bx = __ldg(&bias[col]);
            const float by = __ldg(&bias[col + 1]);
            float2 v0 = make_float2(acc[mt][nt][0] + bx, acc[mt][nt][1] + by);
            float2 v1 = make_float2(acc[mt][nt][2] + bx, acc[mt][nt][3] + by);
            *(float2*)&Y[(size_t)row0 * OUT_N + col] = v0;
            *(float2*)&Y[(size_t)(row0 + 8) * OUT_N + col] = v1;
        }
    }
}

// ---------------- launch ----------------------------------------------------
extern "C" void kernel_launch(void* const* d_in, const int* in_sizes, int n_in,
                              void* d_out, int out_size)
{
    const float* x       = (const float*)d_in[0];  // [4, 2048, 2048]
    const int*   indices = (const int*)  d_in[1];  // [2048, 2048]
    const float* lut     = (const float*)d_in[2];  // [16]
    const float* sA      = (const float*)d_in[3];  // [2048, 4]
    const float* sB      = (const float*)d_in[4];  // [4, 2048]
    const float* mag     = (const float*)d_in[5];  // [4]
    const float* bias    = (const float*)d_in[6];  // [2048]
    float* y = (float*)d_out;                      // [4, 2048, 2048]

    cudaFuncSetAttribute(gemm_kernel, cudaFuncAttributeMaxDynamicSharedMemorySize, DYN_SMEM);

    round_x_kernel<<<(M_ROWS * IN_K) / (256 * 8), 256>>>(x);
    prep_kernel<<<1, 256>>>(sA, sB, mag);
    build_w_kernel<<<OUT_N, 512>>>(indices, lut);

    dim3 grid(OUT_N / BN, M_ROWS / BM);  // (16, 64)
    gemm_kernel<<<grid, 256, DYN_SMEM>>>(bias, y);
}

// round 8
// speedup vs baseline: 6.3282x; 1.1072x over previous
#include <cuda_runtime.h>
#include <cuda_fp16.h>
#include <math.h>
#include <stdint.h>

#define OUT_N  2048
#define IN_K   2048
#define M_ROWS 8192
#define RANK   4

// ---------------- scratch (static device globals; no runtime alloc) --------
__device__ float  g_aScaled[OUT_N * RANK];
__device__ float  g_bScaled[RANK * IN_K];
__device__ __half g_W[(size_t)OUT_N * IN_K];   // fp16 effective weight (8 MB)
__device__ __half g_X[(size_t)M_ROWS * IN_K];  // fp16 activations (32 MB)

__device__ __forceinline__ uint32_t h2_bits(__half2 h) {
    union { __half2 h; uint32_t u; } cvt;
    cvt.h = h;
    return cvt.u;
}

// ---------------- Kernel 1: rank norms + softplus (warp per rank) -----------
__global__ __launch_bounds__(256) void prep_kernel(const float* __restrict__ sA,
                                                   const float* __restrict__ sB,
                                                   const float* __restrict__ mag)
{
    __shared__ float cA[RANK], cB[RANK];
    const int tid = threadIdx.x, wid = tid >> 5, lid = tid & 31;
    if (wid < 4) {
        const int r = wid;
        float s = 0.f;
        for (int o = lid; o < OUT_N; o += 32) { float v = sA[o * RANK + r]; s += v * v; }
        for (int off = 16; off; off >>= 1) s += __shfl_xor_sync(0xffffffff, s, off);
        if (lid == 0) {
            float nrm = fmaxf(sqrtf(s), 1e-6f);
            float m = mag[r];
            float g = (m > 20.f ? m : log1pf(expf(m))) + 1e-6f;
            cA[r] = g / nrm;
        }
    } else {
        const int r = wid - 4;
        float s = 0.f;
        for (int i = lid; i < IN_K; i += 32) { float v = sB[r * IN_K + i]; s += v * v; }
        for (int off = 16; off; off >>= 1) s += __shfl_xor_sync(0xffffffff, s, off);
        if (lid == 0) cB[r] = 1.f / fmaxf(sqrtf(s), 1e-6f);
    }
    __syncthreads();
    for (int idx = tid; idx < OUT_N * RANK; idx += 256)
        g_aScaled[idx] = fabsf(sA[idx]) * cA[idx & 3];
    for (int idx = tid; idx < RANK * IN_K; idx += 256)
        g_bScaled[idx] = fabsf(sB[idx]) * cB[idx >> 11];
}

// ---------------- Kernel 2: W = half(lut[idx] * dot4(a,b)) ------------------
__global__ __launch_bounds__(512) void build_w_kernel(const int* __restrict__ indices,
                                                      const float* __restrict__ lut)
{
    __shared__ float lsh[16];
    __shared__ float ash[RANK];
    const int o = blockIdx.x;
    const int tid = threadIdx.x;
    if (tid < 16) lsh[tid] = lut[tid];
    if (tid < RANK) ash[tid] = g_aScaled[o * RANK + tid];
    __syncthreads();

    const float a0 = ash[0], a1 = ash[1], a2 = ash[2], a3 = ash[3];
    const int i0 = tid * 4;
    const int4 idx = *(const int4*)&indices[(size_t)o * IN_K + i0];
    const float4 b0 = *(const float4*)&g_bScaled[0 * IN_K + i0];
    const float4 b1 = *(const float4*)&g_bScaled[1 * IN_K + i0];
    const float4 b2 = *(const float4*)&g_bScaled[2 * IN_K + i0];
    const float4 b3 = *(const float4*)&g_bScaled[3 * IN_K + i0];

    __half2 w01 = __floats2half2_rn(
        lsh[idx.x] * (a0 * b0.x + a1 * b1.x + a2 * b2.x + a3 * b3.x),
        lsh[idx.y] * (a0 * b0.y + a1 * b1.y + a2 * b2.y + a3 * b3.y));
    __half2 w23 = __floats2half2_rn(
        lsh[idx.z] * (a0 * b0.z + a1 * b1.z + a2 * b2.z + a3 * b3.z),
        lsh[idx.w] * (a0 * b0.w + a1 * b1.w + a2 * b2.w + a3 * b3.w));
    uint2 packed = make_uint2(h2_bits(w01), h2_bits(w23));
    *(uint2*)&g_W[(size_t)o * IN_K + i0] = packed;
}

// ---------------- Kernel 3: X -> fp16 ---------------------------------------
__global__ __launch_bounds__(256) void round_x_kernel(const float* __restrict__ x)
{
    size_t i = ((size_t)blockIdx.x * 256 + threadIdx.x) * 8;
    float4 v0 = *(const float4*)&x[i];
    float4 v1 = *(const float4*)&x[i + 4];
    uint4 out;
    out.x = h2_bits(__floats2half2_rn(v0.x, v0.y));
    out.y = h2_bits(__floats2half2_rn(v0.z, v0.w));
    out.z = h2_bits(__floats2half2_rn(v1.x, v1.y));
    out.w = h2_bits(__floats2half2_rn(v1.z, v1.w));
    *(uint4*)&g_X[i] = out;
}

// ---------------- Kernel 4: fp16 mma.sync GEMM + ldmatrix -------------------
// Y[M,N] = X[M,K] * W[N,K]^T + bias ; CTA tile 128x128, BK=64 halves,
// 3 stages, 2 CTAs/SM, m16n8k16 f16 w/ fp32 acc, ldmatrix.x4 fragment loads.
#define BM 128
#define BN 128
#define BK 64
#define PADH 72                        // halves per smem row (64 + 8 pad = 144B)
#define STG_HALVES ((BM + BN) * PADH)  // 18432 halves per stage
#define STG_BYTES (STG_HALVES * 2)     // 36,864 B
#define AS_OFF 0
#define BS_OFF (BM * PADH)             // 9216 halves
#define NKT (IN_K / BK)                // 32
#define NSTG 3
#define DYN_SMEM (NSTG * STG_BYTES)    // 110,592 B

__device__ __forceinline__ uint32_t smem_u32(const void* p) {
    uint32_t a;
    asm("{ .reg .u64 t; cvta.to.shared.u64 t, %1; cvt.u32.u64 %0, t; }" : "=r"(a) : "l"(p));
    return a;
}
__device__ __forceinline__ void cp16(void* dst, const void* src) {
    uint32_t d;
    asm("{ .reg .u64 t; cvta.to.shared.u64 t, %1; cvt.u32.u64 %0, t; }" : "=r"(d) : "l"(dst));
    asm volatile("cp.async.cg.shared.global [%0], [%1], 16;" :: "r"(d), "l"(src));
}
__device__ __forceinline__ void cp_commit() {
    asm volatile("cp.async.commit_group;" ::: "memory");
}
template<int N>
__device__ __forceinline__ void cp_wait() {
    asm volatile("cp.async.wait_group %0;" :: "n"(N) : "memory");
}
__device__ __forceinline__ void ldsm_x4(uint32_t* r, uint32_t addr) {
    asm volatile("ldmatrix.sync.aligned.m8n8.x4.shared.b16 {%0,%1,%2,%3}, [%4];"
                 : "=r"(r[0]), "=r"(r[1]), "=r"(r[2]), "=r"(r[3]) : "r"(addr));
}
__device__ __forceinline__ void mma16(float& c0, float& c1, float& c2, float& c3,
                                      uint32_t a0, uint32_t a1, uint32_t a2, uint32_t a3,
                                      uint32_t b0, uint32_t b1) {
    asm volatile(
        "mma.sync.aligned.m16n8k16.row.col.f32.f16.f16.f32 "
        "{%0,%1,%2,%3}, {%4,%5,%6,%7}, {%8,%9}, {%0,%1,%2,%3};"
        : "+f"(c0), "+f"(c1), "+f"(c2), "+f"(c3)
        : "r"(a0), "r"(a1), "r"(a2), "r"(a3), "r"(b0), "r"(b1));
}

__device__ __forceinline__ void issue_stage(__half* smem, int stage, int kbase,
                                            const __half* Ag, const __half* Bg, int tid)
{
    __half* as = smem + (size_t)stage * STG_HALVES + AS_OFF;
    __half* bs = smem + (size_t)stage * STG_HALVES + BS_OFF;
#pragma unroll
    for (int i = 0; i < 4; ++i) {
        int c = tid + i * 256, row = c >> 3, kc = (c & 7) << 3;
        cp16(as + row * PADH + kc, Ag + (size_t)row * IN_K + kbase + kc);
    }
#pragma unroll
    for (int i = 0; i < 4; ++i) {
        int c = tid + i * 256, row = c >> 3, kc = (c & 7) << 3;
        cp16(bs + row * PADH + kc, Bg + (size_t)row * IN_K + kbase + kc);
    }
    cp_commit();
}

__global__ __launch_bounds__(256, 2) void gemm_kernel(const float* __restrict__ bias,
                                                      float* __restrict__ Y)
{
    extern __shared__ __half smem[];
    const uint32_t sbase = smem_u32(smem);
    const int tid = threadIdx.x;
    const int wid = tid >> 5, lane = tid & 31;
    const int warp_m = wid & 1, warp_n = wid >> 1;   // 2 x 4 warps; warp tile 64x32
    const int gid = lane >> 2, tig = lane & 3;
    const int bm = blockIdx.y * BM;
    const int bn = blockIdx.x * BN;

    const __half* Ag = g_X + (size_t)bm * IN_K;
    const __half* Bg = g_W + (size_t)bn * IN_K;

    // ldmatrix per-lane base byte offsets
    const int lg = lane >> 3, lr = lane & 7;      // lane group 0..3, row-in-group
    // A x4: g0:(m+0,k+0) g1:(m+8,k+0) g2:(m+0,k+8) g3:(m+8,k+8)
    const uint32_t aLane = (uint32_t)(((warp_m * 64 + (lg & 1) * 8 + lr) * PADH
                                       + (lg >> 1) * 8) * 2);
    // B x4: g0:(n+0,k+0) g1:(n+0,k+8) g2:(n+8,k+0) g3:(n+8,k+8)
    const uint32_t bLane = (uint32_t)(((warp_n * 32 + (lg >> 1) * 8 + lr) * PADH
                                       + (lg & 1) * 8 + BS_OFF) * 2);

    float acc[4][4][4];
#pragma unroll
    for (int i = 0; i < 4; ++i)
#pragma unroll
        for (int j = 0; j < 4; ++j)
#pragma unroll
            for (int q = 0; q < 4; ++q) acc[i][j][q] = 0.f;

    // ---- prologue: stages 0,1 ----
    issue_stage(smem, 0, 0 * BK, Ag, Bg, tid);
    issue_stage(smem, 1, 1 * BK, Ag, Bg, tid);

    for (int kt = 0; kt < NKT; ++kt) {
        cp_wait<1>();          // stage kt%3 resident
        __syncthreads();       // compute of kt-1 done -> stage (kt+2)%3 free

        const int ldk = kt + 2;
        if (ldk < NKT)
            issue_stage(smem, ldk % NSTG, ldk * BK, Ag, Bg, tid);

        const uint32_t stq = sbase + (uint32_t)(kt % NSTG) * STG_BYTES;
        const uint32_t aQ = stq + aLane;
        const uint32_t bQ = stq + bLane;

#pragma unroll
        for (int ks = 0; ks < 4; ++ks) {      // 4 x k16 per BK=64
            const uint32_t kOff = (uint32_t)(ks * 32);  // 16 halves = 32 B
            uint32_t a[4][4];
#pragma unroll
            for (int mt = 0; mt < 4; ++mt)
                ldsm_x4(a[mt], aQ + (uint32_t)(mt * 16 * PADH * 2) + kOff);
            uint32_t bb[2][4];   // bb[j] = {b[2j][0], b[2j][1], b[2j+1][0], b[2j+1][1]}
#pragma unroll
            for (int j = 0; j < 2; ++j)
                ldsm_x4(bb[j], bQ + (uint32_t)(j * 16 * PADH * 2) + kOff);
#pragma unroll
            for (int mt = 0; mt < 4; ++mt)
#pragma unroll
                for (int nt = 0; nt < 4; ++nt)
                    mma16(acc[mt][nt][0], acc[mt][nt][1], acc[mt][nt][2], acc[mt][nt][3],
                          a[mt][0], a[mt][1], a[mt][2], a[mt][3],
                          bb[nt >> 1][(nt & 1) * 2], bb[nt >> 1][(nt & 1) * 2 + 1]);
        }
    }

    // ---- epilogue: bias + store ----
#pragma unroll
    for (int mt = 0; mt < 4; ++mt) {
        const int row0 = bm + warp_m * 64 + mt * 16 + gid;
#pragma unroll
        for (int nt = 0; nt < 4; ++nt) {
            const int col = bn + warp_n * 32 + nt * 8 + tig * 2;
            const float bx = __ldg(&bias[col]);
            const float by = __ldg(&bias[col + 1]);
            float2 v0 = make_float2(acc[mt][nt][0] + bx, acc[mt][nt][1] + by);
            float2 v1 = make_float2(acc[mt][nt][2] + bx, acc[mt][nt][3] + by);
            *(float2*)&Y[(size_t)row0 * OUT_N + col] = v0;
            *(float2*)&Y[(size_t)(row0 + 8) * OUT_N + col] = v1;
        }
    }
}

// ---------------- launch ----------------------------------------------------
extern "C" void kernel_launch(void* const* d_in, const int* in_sizes, int n_in,
                              void* d_out, int out_size)
{
    const float* x       = (const float*)d_in[0];  // [4, 2048, 2048]
    const int*   indices = (const int*)  d_in[1];  // [2048, 2048]
    const float* lut     = (const float*)d_in[2];  // [16]
    const float* sA      = (const float*)d_in[3];  // [2048, 4]
    const float* sB      = (const float*)d_in[4];  // [4, 2048]
    const float* mag     = (const float*)d_in[5];  // [4]
    const float* bias    = (const float*)d_in[6];  // [2048]
    float* y = (float*)d_out;                      // [4, 2048, 2048]

    cudaFuncSetAttribute(gemm_kernel, cudaFuncAttributeMaxDynamicSharedMemorySize, DYN_SMEM);

    round_x_kernel<<<(M_ROWS * IN_K) / (256 * 8), 256>>>(x);
    prep_kernel<<<1, 256>>>(sA, sB, mag);
    build_w_kernel<<<OUT_N, 512>>>(indices, lut);

    dim3 grid(OUT_N / BN, M_ROWS / BM);  // (16, 64)
    gemm_kernel<<<grid, 256, DYN_SMEM>>>(bias, y);
}

// round 9
// speedup vs baseline: 6.4413x; 1.0179x over previous
#include <cuda_runtime.h>
#include <cuda_fp16.h>
#include <math.h>
#include <stdint.h>

#define OUT_N  2048
#define IN_K   2048
#define M_ROWS 8192
#define RANK   4

// ---------------- scratch (static device globals; no runtime alloc) --------
__device__ float  g_coef[8];                   // [0..3]=g_r/||A_r||, [4..7]=1/||B_r||
__device__ __half g_W[(size_t)OUT_N * IN_K];   // fp16 effective weight (8 MB)
__device__ __half g_X[(size_t)M_ROWS * IN_K];  // fp16 activations (32 MB)

__device__ __forceinline__ uint32_t h2_bits(__half2 h) {
    union { __half2 h; uint32_t u; } cvt;
    cvt.h = h;
    return cvt.u;
}

// ---------------- Kernel 1: 8 blocks, one norm each -------------------------
__global__ __launch_bounds__(256) void norm_kernel(const float* __restrict__ sA,
                                                   const float* __restrict__ sB,
                                                   const float* __restrict__ mag)
{
    __shared__ float red[8];
    const int r = blockIdx.x;        // 0..7
    const int tid = threadIdx.x, lid = tid & 31, wid = tid >> 5;
    float s = 0.f;
    if (r < 4) {
        for (int o = tid; o < OUT_N; o += 256) { float v = sA[o * RANK + r]; s += v * v; }
    } else {
        const float* row = sB + (size_t)(r - 4) * IN_K;
        for (int i = tid; i < IN_K; i += 256) { float v = row[i]; s += v * v; }
    }
    for (int off = 16; off; off >>= 1) s += __shfl_xor_sync(0xffffffff, s, off);
    if (lid == 0) red[wid] = s;
    __syncthreads();
    if (tid == 0) {
        float t = 0.f;
        for (int w = 0; w < 8; ++w) t += red[w];
        float nrm = fmaxf(sqrtf(t), 1e-6f);
        if (r < 4) {
            float m = mag[r];
            float g = (m > 20.f ? m : log1pf(expf(m))) + 1e-6f;
            g_coef[r] = g / nrm;
        } else {
            g_coef[r] = 1.f / nrm;
        }
    }
}

// ---------------- Kernel 2: W = half(lut[idx] * dot4(|a|c, |b|c)) -----------
__global__ __launch_bounds__(512) void build_w_kernel(const int* __restrict__ indices,
                                                      const float* __restrict__ lut,
                                                      const float* __restrict__ sA,
                                                      const float* __restrict__ sB)
{
    __shared__ float lsh[16];
    __shared__ float ash[RANK];
    const int o = blockIdx.x;
    const int tid = threadIdx.x;
    if (tid < 16) lsh[tid] = lut[tid];
    if (tid < RANK) ash[tid] = fabsf(sA[o * RANK + tid]) * g_coef[tid];
    __syncthreads();

    const float a0 = ash[0], a1 = ash[1], a2 = ash[2], a3 = ash[3];
    const float c0 = g_coef[4], c1 = g_coef[5], c2 = g_coef[6], c3 = g_coef[7];
    const int i0 = tid * 4;
    const int4 idx = *(const int4*)&indices[(size_t)o * IN_K + i0];
    const float4 b0 = *(const float4*)&sB[0 * IN_K + i0];
    const float4 b1 = *(const float4*)&sB[1 * IN_K + i0];
    const float4 b2 = *(const float4*)&sB[2 * IN_K + i0];
    const float4 b3 = *(const float4*)&sB[3 * IN_K + i0];

    const float k0 = a0 * c0, k1 = a1 * c1, k2 = a2 * c2, k3 = a3 * c3;
    __half2 w01 = __floats2half2_rn(
        lsh[idx.x] * (k0 * fabsf(b0.x) + k1 * fabsf(b1.x) + k2 * fabsf(b2.x) + k3 * fabsf(b3.x)),
        lsh[idx.y] * (k0 * fabsf(b0.y) + k1 * fabsf(b1.y) + k2 * fabsf(b2.y) + k3 * fabsf(b3.y)));
    __half2 w23 = __floats2half2_rn(
        lsh[idx.z] * (k0 * fabsf(b0.z) + k1 * fabsf(b1.z) + k2 * fabsf(b2.z) + k3 * fabsf(b3.z)),
        lsh[idx.w] * (k0 * fabsf(b0.w) + k1 * fabsf(b1.w) + k2 * fabsf(b2.w) + k3 * fabsf(b3.w)));
    uint2 packed = make_uint2(h2_bits(w01), h2_bits(w23));
    *(uint2*)&g_W[(size_t)o * IN_K + i0] = packed;
}

// ---------------- Kernel 3: X -> fp16 ---------------------------------------
__global__ __launch_bounds__(256) void round_x_kernel(const float* __restrict__ x)
{
    size_t i = ((size_t)blockIdx.x * 256 + threadIdx.x) * 8;
    float4 v0 = *(const float4*)&x[i];
    float4 v1 = *(const float4*)&x[i + 4];
    uint4 out;
    out.x = h2_bits(__floats2half2_rn(v0.x, v0.y));
    out.y = h2_bits(__floats2half2_rn(v0.z, v0.w));
    out.z = h2_bits(__floats2half2_rn(v1.x, v1.y));
    out.w = h2_bits(__floats2half2_rn(v1.z, v1.w));
    *(uint4*)&g_X[i] = out;
}

// ---------------- Kernel 4: fp16 mma.sync GEMM + ldmatrix + dbuf ------------
#define BM 128
#define BN 128
#define BK 64
#define PADH 72                        // halves per smem row (64 + 8 pad = 144B)
#define STG_HALVES ((BM + BN) * PADH)
#define STG_BYTES (STG_HALVES * 2)     // 36,864 B
#define AS_OFF 0
#define BS_OFF (BM * PADH)
#define NKT (IN_K / BK)                // 32
#define NSTG 3
#define DYN_SMEM (NSTG * STG_BYTES)    // 110,592 B

__device__ __forceinline__ uint32_t smem_u32(const void* p) {
    uint32_t a;
    asm("{ .reg .u64 t; cvta.to.shared.u64 t, %1; cvt.u32.u64 %0, t; }" : "=r"(a) : "l"(p));
    return a;
}
__device__ __forceinline__ void cp16(void* dst, const void* src) {
    uint32_t d;
    asm("{ .reg .u64 t; cvta.to.shared.u64 t, %1; cvt.u32.u64 %0, t; }" : "=r"(d) : "l"(dst));
    asm volatile("cp.async.cg.shared.global [%0], [%1], 16;" :: "r"(d), "l"(src));
}
__device__ __forceinline__ void cp_commit() {
    asm volatile("cp.async.commit_group;" ::: "memory");
}
template<int N>
__device__ __forceinline__ void cp_wait() {
    asm volatile("cp.async.wait_group %0;" :: "n"(N) : "memory");
}
__device__ __forceinline__ void ldsm_x4(uint32_t* r, uint32_t addr) {
    asm volatile("ldmatrix.sync.aligned.m8n8.x4.shared.b16 {%0,%1,%2,%3}, [%4];"
                 : "=r"(r[0]), "=r"(r[1]), "=r"(r[2]), "=r"(r[3]) : "r"(addr));
}
__device__ __forceinline__ void mma16(float& c0, float& c1, float& c2, float& c3,
                                      uint32_t a0, uint32_t a1, uint32_t a2, uint32_t a3,
                                      uint32_t b0, uint32_t b1) {
    asm volatile(
        "mma.sync.aligned.m16n8k16.row.col.f32.f16.f16.f32 "
        "{%0,%1,%2,%3}, {%4,%5,%6,%7}, {%8,%9}, {%0,%1,%2,%3};"
        : "+f"(c0), "+f"(c1), "+f"(c2), "+f"(c3)
        : "r"(a0), "r"(a1), "r"(a2), "r"(a3), "r"(b0), "r"(b1));
}

__device__ __forceinline__ void issue_stage(__half* smem, int stage, int kbase,
                                            const __half* Ag, const __half* Bg, int tid)
{
    __half* as = smem + (size_t)stage * STG_HALVES + AS_OFF;
    __half* bs = smem + (size_t)stage * STG_HALVES + BS_OFF;
#pragma unroll
    for (int i = 0; i < 4; ++i) {
        int c = tid + i * 256, row = c >> 3, kc = (c & 7) << 3;
        cp16(as + row * PADH + kc, Ag + (size_t)row * IN_K + kbase + kc);
    }
#pragma unroll
    for (int i = 0; i < 4; ++i) {
        int c = tid + i * 256, row = c >> 3, kc = (c & 7) << 3;
        cp16(bs + row * PADH + kc, Bg + (size_t)row * IN_K + kbase + kc);
    }
    cp_commit();
}

__device__ __forceinline__ void load_frags(uint32_t aQ, uint32_t bQ, int ks,
                                           uint32_t (*a)[4], uint32_t (*bb)[4])
{
    const uint32_t kOff = (uint32_t)(ks * 32);
#pragma unroll
    for (int mt = 0; mt < 4; ++mt)
        ldsm_x4(a[mt], aQ + (uint32_t)(mt * 16 * PADH * 2) + kOff);
#pragma unroll
    for (int j = 0; j < 2; ++j)
        ldsm_x4(bb[j], bQ + (uint32_t)(j * 16 * PADH * 2) + kOff);
}

__global__ __launch_bounds__(256, 2) void gemm_kernel(const float* __restrict__ bias,
                                                      float* __restrict__ Y)
{
    extern __shared__ __half smem[];
    const uint32_t sbase = smem_u32(smem);
    const int tid = threadIdx.x;
    const int wid = tid >> 5, lane = tid & 31;
    const int warp_m = wid & 1, warp_n = wid >> 1;
    const int gid = lane >> 2, tig = lane & 3;
    const int bm = blockIdx.y * BM;
    const int bn = blockIdx.x * BN;

    const __half* Ag = g_X + (size_t)bm * IN_K;
    const __half* Bg = g_W + (size_t)bn * IN_K;

    const int lg = lane >> 3, lr = lane & 7;
    const uint32_t aLane = (uint32_t)(((warp_m * 64 + (lg & 1) * 8 + lr) * PADH
                                       + (lg >> 1) * 8) * 2);
    const uint32_t bLane = (uint32_t)(((warp_n * 32 + (lg >> 1) * 8 + lr) * PADH
                                       + (lg & 1) * 8 + BS_OFF) * 2);

    float acc[4][4][4];
#pragma unroll
    for (int i = 0; i < 4; ++i)
#pragma unroll
        for (int j = 0; j < 4; ++j)
#pragma unroll
            for (int q = 0; q < 4; ++q) acc[i][j][q] = 0.f;

    issue_stage(smem, 0, 0 * BK, Ag, Bg, tid);
    issue_stage(smem, 1, 1 * BK, Ag, Bg, tid);

    uint32_t a[2][4][4], bb[2][2][4];

    for (int kt = 0; kt < NKT; ++kt) {
        cp_wait<1>();
        __syncthreads();

        const int ldk = kt + 2;
        if (ldk < NKT)
            issue_stage(smem, ldk % NSTG, ldk * BK, Ag, Bg, tid);

        const uint32_t stq = sbase + (uint32_t)(kt % NSTG) * STG_BYTES;
        const uint32_t aQ = stq + aLane;
        const uint32_t bQ = stq + bLane;

        load_frags(aQ, bQ, 0, a[0], bb[0]);
#pragma unroll
        for (int ks = 0; ks < 4; ++ks) {
            const int cur = ks & 1;
            if (ks < 3)
                load_frags(aQ, bQ, ks + 1, a[cur ^ 1], bb[cur ^ 1]);
#pragma unroll
            for (int mt = 0; mt < 4; ++mt)
#pragma unroll
                for (int nt = 0; nt < 4; ++nt)
                    mma16(acc[mt][nt][0], acc[mt][nt][1], acc[mt][nt][2], acc[mt][nt][3],
                          a[cur][mt][0], a[cur][mt][1], a[cur][mt][2], a[cur][mt][3],
                          bb[cur][nt >> 1][(nt & 1) * 2], bb[cur][nt >> 1][(nt & 1) * 2 + 1]);
        }
    }

    // ---- epilogue: bias + store ----
#pragma unroll
    for (int mt = 0; mt < 4; ++mt) {
        const int row0 = bm + warp_m * 64 + mt * 16 + gid;
#pragma unroll
        for (int nt = 0; nt < 4; ++nt) {
            const int col = bn + warp_n * 32 + nt * 8 + tig * 2;
            const float bx = __ldg(&bias[col]);
            const float by = __ldg(&bias[col + 1]);
            float2 v0 = make_float2(acc[mt][nt][0] + bx, acc[mt][nt][1] + by);
            float2 v1 = make_float2(acc[mt][nt][2] + bx, acc[mt][nt][3] + by);
            *(float2*)&Y[(size_t)row0 * OUT_N + col] = v0;
            *(float2*)&Y[(size_t)(row0 + 8) * OUT_N + col] = v1;
        }
    }
}

// ---------------- launch ----------------------------------------------------
extern "C" void kernel_launch(void* const* d_in, const int* in_sizes, int n_in,
                              void* d_out, int out_size)
{
    const float* x       = (const float*)d_in[0];  // [4, 2048, 2048]
    const int*   indices = (const int*)  d_in[1];  // [2048, 2048]
    const float* lut     = (const float*)d_in[2];  // [16]
    const float* sA      = (const float*)d_in[3];  // [2048, 4]
    const float* sB      = (const float*)d_in[4];  // [4, 2048]
    const float* mag     = (const float*)d_in[5];  // [4]
    const float* bias    = (const float*)d_in[6];  // [2048]
    float* y = (float*)d_out;                      // [4, 2048, 2048]

    cudaFuncSetAttribute(gemm_kernel, cudaFuncAttributeMaxDynamicSharedMemorySize, DYN_SMEM);

    round_x_kernel<<<(M_ROWS * IN_K) / (256 * 8), 256>>>(x);
    norm_kernel<<<8, 256>>>(sA, sB, mag);
    build_w_kernel<<<OUT_N, 512>>>(indices, lut, sA, sB);

    dim3 grid(OUT_N / BN, M_ROWS / BM);  // (16, 64)
    gemm_kernel<<<grid, 256, DYN_SMEM>>>(bias, y);
}